// round 7
// baseline (speedup 1.0000x reference)
#include <cuda_runtime.h>

// ============================================================================
// QCNN 8-qubit circuit — exact algebraic reduction to a 3x3 bilinear form,
// single fused kernel, 4 elements/thread (one 128B x-line per thread,
// float4 output store), 128 CTAs x 128 threads (one CTA per SM, one wave).
//
// Math (verified R1-R6, rel_err ~1e-7): CNOTs couple only disjoint qubit
// pairs; <Z_0> depends only on the (0,1) 2-qubit subsystem; batch-independent
// params make the 3-layer circuit one fixed 4x4 complex unitary W; with the
// real product input state and double-angle identities:
//     z   = (1, cos x0, sin x0) · M · (1, cos x1, sin x1)^T,  M real 3x3
//     out = sigmoid(weight * z)      (weight folded into M)
// ============================================================================

__global__ void __launch_bounds__(128) qcnn_fused_kernel(
    const float* __restrict__ x,
    const float* __restrict__ params,
    const float* __restrict__ weight,
    float* __restrict__ out,
    int n)
{
    __shared__ float sTrig[3][12];      // per layer: w0 cb,sb,cp,sp,cm,sm; w1 same
    __shared__ float sWre[3][16], sWim[3][16];
    __shared__ float sM[9];

    int tid = threadIdx.x;
    int t = blockIdx.x * 128 + tid;     // thread id over n/4 threads
    int i0 = t * 4;                     // first of 4 consecutive rows

    // ---- Issue all 4 independent x-loads FIRST (MLP=4, one 128B line) -----
    float2 xv0 = make_float2(0.0f, 0.0f);
    float2 xv1 = xv0, xv2 = xv0, xv3 = xv0;
    if (i0 + 3 < n) {
        const float* base = x + (size_t)i0 * 8;
        xv0 = *reinterpret_cast<const float2*>(base + 0);
        xv1 = *reinterpret_cast<const float2*>(base + 8);
        xv2 = *reinterpret_cast<const float2*>(base + 16);
        xv3 = *reinterpret_cast<const float2*>(base + 24);
    }

    // ---- warp 0: build M (verified R6 structure, ~0 marginal cost) --------
    if (tid < 32) {
        const unsigned FULL = 0xFFFFFFFFu;
        int lane = tid;

        if (lane < 18) {
            int l = lane / 6, rem = lane - l * 6;
            int q = rem / 3, combo = rem - q * 3;
            const float* p = params + l * 24 + q * 3;   // a,b,g contiguous
            float ang;
            if (combo == 0)      ang = 0.5f * p[1];              // b/2
            else if (combo == 1) ang = 0.5f * (p[0] + p[2]);     // (a+g)/2
            else                 ang = 0.5f * (p[0] - p[2]);     // (a-g)/2
            float s, c;
            __sincosf(ang, &s, &c);
            sTrig[l][q * 6 + combo * 2 + 0] = c;
            sTrig[l][q * 6 + combo * 2 + 1] = s;
        }
        float wgt = __ldg(weight);
        __syncwarp();

        // W chain: lanes 0..15 own element (r,c); CNOT folded via sr.
        int r = (lane >> 2) & 3, c = lane & 3;
        int sr = (r >= 2) ? (5 - r) : r;        // 0,1,3,2
        int q0 = sr >> 1, q1 = sr & 1;

        float wre = 0.0f, wim = 0.0f;
        #pragma unroll
        for (int l = 0; l < 3; l++) {
            float cb0 = sTrig[l][0],  sb0 = sTrig[l][1];
            float cp0 = sTrig[l][2],  sp0 = sTrig[l][3];
            float cm0 = sTrig[l][4],  sm0 = sTrig[l][5];
            float cb1 = sTrig[l][6],  sb1 = sTrig[l][7];
            float cp1 = sTrig[l][8],  sp1 = sTrig[l][9];
            float cm1 = sTrig[l][10], sm1 = sTrig[l][11];

            float a0r, a0i, a1r, a1i;        // U0[q0][0], U0[q0][1]
            if (q0 == 0) { a0r =  cb0*cp0; a0i = -cb0*sp0; a1r = -sb0*cm0; a1i = -sb0*sm0; }
            else         { a0r =  sb0*cm0; a0i = -sb0*sm0; a1r =  cb0*cp0; a1i =  cb0*sp0; }
            float b0r, b0i, b1r, b1i;        // U1[q1][0], U1[q1][1]
            if (q1 == 0) { b0r =  cb1*cp1; b0i = -cb1*sp1; b1r = -sb1*cm1; b1i = -sb1*sm1; }
            else         { b0r =  sb1*cm1; b0i = -sb1*sm1; b1r =  cb1*cp1; b1i =  cb1*sp1; }

            float Kre[4], Kim[4];            // K_eff[k] = U0[q0][k>>1]*U1[q1][k&1]
            Kre[0] = a0r*b0r - a0i*b0i;  Kim[0] = a0r*b0i + a0i*b0r;
            Kre[1] = a0r*b1r - a0i*b1i;  Kim[1] = a0r*b1i + a0i*b1r;
            Kre[2] = a1r*b0r - a1i*b0i;  Kim[2] = a1r*b0i + a1i*b0r;
            Kre[3] = a1r*b1r - a1i*b1i;  Kim[3] = a1r*b1i + a1i*b1r;

            if (l == 0) {
                wre = Kre[c];  wim = Kim[c];           // W_prev = I
            } else {
                if (lane < 16) { sWre[l][lane] = wre; sWim[l][lane] = wim; }
                __syncwarp();
                float ar = 0.0f, ai = 0.0f;
                #pragma unroll
                for (int k = 0; k < 4; k++) {
                    float br = sWre[l][k * 4 + c], bi = sWim[l][k * 4 + c];
                    ar = fmaf(Kre[k], br, fmaf(-Kim[k], bi, ar));
                    ai = fmaf(Kre[k], bi, fmaf( Kim[k], br, ai));
                }
                wre = ar;  wim = ai;
            }
        }

        if (lane < 16) { sWre[0][lane] = wre; sWim[0][lane] = wim; }
        __syncwarp();

        // Lane-parallel S: lane a*4+b computes S[a][b], d=(+,+,-,-).
        int a = (lane >> 2) & 3, b = lane & 3;
        float s_ab = 0.0f;
        #pragma unroll
        for (int rr = 0; rr < 4; rr++) {
            float tt = fmaf(sWre[0][rr * 4 + a], sWre[0][rr * 4 + b],
                            sWim[0][rr * 4 + a] * sWim[0][rr * 4 + b]);
            s_ab += (rr < 2) ? tt : -tt;
        }

        float s00 = __shfl_sync(FULL, s_ab, 0);
        float s11 = __shfl_sync(FULL, s_ab, 5);
        float s22 = __shfl_sync(FULL, s_ab, 10);
        float s33 = __shfl_sync(FULL, s_ab, 15);
        float s01 = __shfl_sync(FULL, s_ab, 1);
        float s23 = __shfl_sync(FULL, s_ab, 11);
        float s02 = __shfl_sync(FULL, s_ab, 2);
        float s13 = __shfl_sync(FULL, s_ab, 7);
        float s03 = __shfl_sync(FULL, s_ab, 3);
        float s12 = __shfl_sync(FULL, s_ab, 6);

        if (lane == 0) {
            float q4 = 0.25f * wgt, q2 = 0.5f * wgt;
            sM[0] = q4 * (s00 + s11 + s22 + s33);   // M00
            sM[1] = q4 * (s00 - s11 + s22 - s33);   // M01
            sM[2] = q2 * (s01 + s23);               // M02
            sM[3] = q4 * (s00 + s11 - s22 - s33);   // M10
            sM[4] = q4 * (s00 - s11 - s22 + s33);   // M11
            sM[5] = q2 * (s01 - s23);               // M12
            sM[6] = q2 * (s02 + s13);               // M20
            sM[7] = q2 * (s02 - s13);               // M21
            sM[8] = q2 * (s03 + s12);               // M22
        }
    }

    // ---- per-element trig, independent of build (8 sincos, all parallel) --
    float Sa0, Ca0, Sb0, Cb0;  __sincosf(xv0.x, &Sa0, &Ca0);  __sincosf(xv0.y, &Sb0, &Cb0);
    float Sa1, Ca1, Sb1, Cb1;  __sincosf(xv1.x, &Sa1, &Ca1);  __sincosf(xv1.y, &Sb1, &Cb1);
    float Sa2, Ca2, Sb2, Cb2;  __sincosf(xv2.x, &Sa2, &Ca2);  __sincosf(xv2.y, &Sb2, &Cb2);
    float Sa3, Ca3, Sb3, Cb3;  __sincosf(xv3.x, &Sa3, &Ca3);  __sincosf(xv3.y, &Sb3, &Cb3);

    __syncthreads();

    float m00 = sM[0], m01 = sM[1], m02 = sM[2];
    float m10 = sM[3], m11 = sM[4], m12 = sM[5];
    float m20 = sM[6], m21 = sM[7], m22 = sM[8];

    if (i0 + 3 >= n) {
        // Generic tail (not hit for n=65536, kept for safety).
        for (int k = 0; k < 4; k++) {
            int i = i0 + k;
            if (i >= n) return;
            float2 xv = *reinterpret_cast<const float2*>(x + (size_t)i * 8);
            float S0, C0, S1, C1;
            __sincosf(xv.x, &S0, &C0);
            __sincosf(xv.y, &S1, &C1);
            float t0 = fmaf(m02, S1, fmaf(m01, C1, m00));
            float t1 = fmaf(m12, S1, fmaf(m11, C1, m10));
            float t2 = fmaf(m22, S1, fmaf(m21, C1, m20));
            float z  = fmaf(S0, t2, fmaf(C0, t1, t0));
            out[i] = __fdividef(1.0f, 1.0f + __expf(-z));
        }
        return;
    }

    // z_k = (1,Ca,Sa) M (1,Cb,Sb)^T, 4 independent chains.
    float z0, z1, z2, z3;
    {
        float t0 = fmaf(m02, Sb0, fmaf(m01, Cb0, m00));
        float t1 = fmaf(m12, Sb0, fmaf(m11, Cb0, m10));
        float t2 = fmaf(m22, Sb0, fmaf(m21, Cb0, m20));
        z0 = fmaf(Sa0, t2, fmaf(Ca0, t1, t0));
    }
    {
        float t0 = fmaf(m02, Sb1, fmaf(m01, Cb1, m00));
        float t1 = fmaf(m12, Sb1, fmaf(m11, Cb1, m10));
        float t2 = fmaf(m22, Sb1, fmaf(m21, Cb1, m20));
        z1 = fmaf(Sa1, t2, fmaf(Ca1, t1, t0));
    }
    {
        float t0 = fmaf(m02, Sb2, fmaf(m01, Cb2, m00));
        float t1 = fmaf(m12, Sb2, fmaf(m11, Cb2, m10));
        float t2 = fmaf(m22, Sb2, fmaf(m21, Cb2, m20));
        z2 = fmaf(Sa2, t2, fmaf(Ca2, t1, t0));
    }
    {
        float t0 = fmaf(m02, Sb3, fmaf(m01, Cb3, m00));
        float t1 = fmaf(m12, Sb3, fmaf(m11, Cb3, m10));
        float t2 = fmaf(m22, Sb3, fmaf(m21, Cb3, m20));
        z3 = fmaf(Sa3, t2, fmaf(Ca3, t1, t0));
    }

    float4 o;
    o.x = __fdividef(1.0f, 1.0f + __expf(-z0));
    o.y = __fdividef(1.0f, 1.0f + __expf(-z1));
    o.z = __fdividef(1.0f, 1.0f + __expf(-z2));
    o.w = __fdividef(1.0f, 1.0f + __expf(-z3));
    *reinterpret_cast<float4*>(out + i0) = o;
}

extern "C" void kernel_launch(void* const* d_in, const int* in_sizes, int n_in,
                              void* d_out, int out_size) {
    const float* x      = (const float*)d_in[0];   // (65536, 8) fp32
    const float* params = (const float*)d_in[1];   // (3, 8, 3) fp32
    const float* weight = (const float*)d_in[2];   // scalar fp32
    float* out = (float*)d_out;                    // (65536,) fp32

    int n = in_sizes[0] / 8;                       // 65536
    int nthreads = (n + 3) / 4;                    // 16384 threads, 4 elems each

    int threads = 128;
    int blocks = (nthreads + threads - 1) / threads;   // 128 blocks
    qcnn_fused_kernel<<<blocks, threads>>>(x, params, weight, out, n);
}